// round 5
// baseline (speedup 1.0000x reference)
#include <cuda_runtime.h>

// Problem constants (fixed by the dataset)
#define NN 20000
#define EE 320000
#define DD 128
#define KK 8
#define HH 64
#define KHD 512   // K*H

typedef unsigned long long ull;
// packed fp32x2 helpers (sm_103a; PTX-only forms)
#define DUP2(o, f)  asm("mov.b64 %0, {%1, %1};" : "=l"(o) : "r"(__float_as_uint(f)))
#define FMA2(d, a, b, c) asm("fma.rn.f32x2 %0, %1, %2, %3;" : "=l"(d) : "l"(a), "l"(b), "l"(c))

// ---------------- scratch (__device__ globals; no allocations) -------------
// g_cnt and g_denom are zeroed at module load and re-zeroed at the END of
// node_kernel each run, so every graph replay starts from a clean state.
__device__ float g_x[(size_t)EE * DD];      // mean edge features (E,128)
__device__ float g_w[EE * KK];              // exp(leakyrelu(logit))
__device__ float g_er[NN * KK];             // node_feat @ W_r^T
__device__ float g_v[DD * KK];              // W_enc folded with attn_l
__device__ float g_denom[NN * KK];          // softmax denominators
__device__ float g_y[(size_t)NN * KK * DD]; // per-node weighted x sums (N,8,128)
__device__ int   g_cnt[NN];
__device__ int   g_off[NN];
__device__ int   g_cur[NN];
__device__ int   g_perm[EE];

// ---------------- CSR scan + fill ------------------------------------------
// single-block exclusive scan over 20000 counts (1024 threads x 20 chunk)
__global__ void scan_kernel() {
    __shared__ int s[1024];
    const int CH = 20;
    int tid = threadIdx.x;
    int start = tid * CH;
    int lsum = 0;
    for (int i = 0; i < CH; i++) {
        int idx = start + i;
        if (idx < NN) lsum += g_cnt[idx];
    }
    s[tid] = lsum;
    __syncthreads();
    for (int o = 1; o < 1024; o <<= 1) {
        int v = (tid >= o) ? s[tid - o] : 0;
        __syncthreads();
        s[tid] += v;
        __syncthreads();
    }
    int run = s[tid] - lsum;
    for (int i = 0; i < CH; i++) {
        int idx = start + i;
        if (idx < NN) {
            g_off[idx] = run;
            g_cur[idx] = run;
            run += g_cnt[idx];
        }
    }
}

__global__ void fill_kernel(const int* __restrict__ dst) {
    int e = blockIdx.x * blockDim.x + threadIdx.x;
    if (e < EE) {
        int pos = atomicAdd(&g_cur[dst[e]], 1);
        g_perm[pos] = e;
    }
}

// ---------------- small precomputes ---------------------------------------
// v[d,k] = sum_h W_enc[d, k*H+h] * attn_l[k,h]
__global__ void v_kernel(const float* __restrict__ W_enc,
                         const float* __restrict__ attn_l) {
    int i = threadIdx.x;          // 1024 threads = 128*8
    int d = i >> 3, k = i & 7;
    float s = 0.f;
    #pragma unroll 8
    for (int h = 0; h < HH; h++)
        s += W_enc[(size_t)d * KHD + k * HH + h] * attn_l[k * HH + h];
    g_v[d * KK + k] = s;
}

// fused: degree count (thread-per-edge) + er[n,k] (warp-per-node)
__global__ void er_count_kernel(const float* __restrict__ nf,
                                const float* __restrict__ W_r,
                                const int* __restrict__ dst) {
    int gtid = blockIdx.x * blockDim.x + threadIdx.x;
    if (gtid < EE) atomicAdd(&g_cnt[dst[gtid]], 1);

    int w = threadIdx.x >> 5;
    int lane = threadIdx.x & 31;
    int n = blockIdx.x * 8 + w;
    if (n >= NN) return;
    const float* row = nf + (size_t)n * DD;
    float a0 = row[lane], a1 = row[lane + 32], a2 = row[lane + 64], a3 = row[lane + 96];
    #pragma unroll
    for (int k = 0; k < KK; k++) {
        const float* wr = W_r + k * DD;
        float v = a0 * wr[lane] + a1 * wr[lane + 32] + a2 * wr[lane + 64] + a3 * wr[lane + 96];
        #pragma unroll
        for (int o = 16; o > 0; o >>= 1) v += __shfl_xor_sync(0xffffffffu, v, o);
        if (lane == 0) g_er[n * KK + k] = v;
    }
}

// ---------------- edge pass (warp-per-edge, float4, reg v, 2-deep pipe) ----
__global__ __launch_bounds__(128) void edge_kernel(const float4* __restrict__ ef4,
                                                   const int* __restrict__ dst) {
    int lane = threadIdx.x & 31;
    int gw = (blockIdx.x * blockDim.x + threadIdx.x) >> 5;
    int nw = (gridDim.x * blockDim.x) >> 5;

    const float4* gv4 = (const float4*)g_v;
    float4 vv0[4], vv1[4];
    #pragma unroll
    for (int dd = 0; dd < 4; dd++) {
        vv0[dd] = gv4[(4 * lane + dd) * 2 + 0];
        vv1[dd] = gv4[(4 * lane + dd) * 2 + 1];
    }
    int b4 = (lane >> 4) & 1, b3 = (lane >> 3) & 1, b2 = (lane >> 2) & 1;
    int myk = b4 * 4 + b3 * 2 + b2;
    float4* gx4 = (float4*)g_x;
    const float inv3 = 1.0f / 3.0f;

    if (gw >= EE) return;
    const float4* base = ef4 + (size_t)gw * 96;
    float4 c0 = base[lane];
    float4 c1 = base[lane + 32];
    float4 c2 = base[lane + 64];
    int cnd = dst[gw];

    for (int e = gw; e < EE; e += nw) {
        int e2 = e + nw;
        int ep = (e2 < EE) ? e2 : e;
        const float4* nbase = ef4 + (size_t)ep * 96;
        float4 n0 = nbase[lane];
        float4 n1 = nbase[lane + 32];
        float4 n2 = nbase[lane + 64];
        int nnd = dst[ep];

        float4 x;
        x.x = (c0.x + c1.x + c2.x) * inv3;
        x.y = (c0.y + c1.y + c2.y) * inv3;
        x.z = (c0.z + c1.z + c2.z) * inv3;
        x.w = (c0.w + c1.w + c2.w) * inv3;
        gx4[(size_t)e * 32 + lane] = x;

        float a[8];
        a[0] = x.x * vv0[0].x + x.y * vv0[1].x + x.z * vv0[2].x + x.w * vv0[3].x;
        a[1] = x.x * vv0[0].y + x.y * vv0[1].y + x.z * vv0[2].y + x.w * vv0[3].y;
        a[2] = x.x * vv0[0].z + x.y * vv0[1].z + x.z * vv0[2].z + x.w * vv0[3].z;
        a[3] = x.x * vv0[0].w + x.y * vv0[1].w + x.z * vv0[2].w + x.w * vv0[3].w;
        a[4] = x.x * vv1[0].x + x.y * vv1[1].x + x.z * vv1[2].x + x.w * vv1[3].x;
        a[5] = x.x * vv1[0].y + x.y * vv1[1].y + x.z * vv1[2].y + x.w * vv1[3].y;
        a[6] = x.x * vv1[0].z + x.y * vv1[1].z + x.z * vv1[2].z + x.w * vv1[3].z;
        a[7] = x.x * vv1[0].w + x.y * vv1[1].w + x.z * vv1[2].w + x.w * vv1[3].w;

        #pragma unroll
        for (int j = 0; j < 4; j++) {
            float keep = b4 ? a[j + 4] : a[j];
            float send = b4 ? a[j] : a[j + 4];
            a[j] = keep + __shfl_xor_sync(0xffffffffu, send, 16);
        }
        #pragma unroll
        for (int j = 0; j < 2; j++) {
            float keep = b3 ? a[j + 2] : a[j];
            float send = b3 ? a[j] : a[j + 2];
            a[j] = keep + __shfl_xor_sync(0xffffffffu, send, 8);
        }
        {
            float keep = b2 ? a[1] : a[0];
            float send = b2 ? a[0] : a[1];
            a[0] = keep + __shfl_xor_sync(0xffffffffu, send, 4);
        }
        a[0] += __shfl_xor_sync(0xffffffffu, a[0], 2);
        a[0] += __shfl_xor_sync(0xffffffffu, a[0], 1);

        if ((lane & 3) == 0) {
            float z = a[0] + g_er[cnd * KK + myk];
            z = (z > 0.f) ? z : 0.01f * z;            // leaky relu
            float wv = __expf(z);                     // shift-free softmax weight
            g_w[e * KK + myk] = wv;
            atomicAdd(&g_denom[cnd * KK + myk], wv);
        }

        c0 = n0; c1 = n1; c2 = n2; cnd = nnd;
    }
}

// ---------------- per-node weighted x aggregation (warp-per-NODE) ----------
static __device__ __forceinline__ void fma8(float4 acc[8], float4 xd, float4 wa, float4 wb) {
    acc[0].x = fmaf(wa.x, xd.x, acc[0].x); acc[0].y = fmaf(wa.x, xd.y, acc[0].y);
    acc[0].z = fmaf(wa.x, xd.z, acc[0].z); acc[0].w = fmaf(wa.x, xd.w, acc[0].w);
    acc[1].x = fmaf(wa.y, xd.x, acc[1].x); acc[1].y = fmaf(wa.y, xd.y, acc[1].y);
    acc[1].z = fmaf(wa.y, xd.z, acc[1].z); acc[1].w = fmaf(wa.y, xd.w, acc[1].w);
    acc[2].x = fmaf(wa.z, xd.x, acc[2].x); acc[2].y = fmaf(wa.z, xd.y, acc[2].y);
    acc[2].z = fmaf(wa.z, xd.z, acc[2].z); acc[2].w = fmaf(wa.z, xd.w, acc[2].w);
    acc[3].x = fmaf(wa.w, xd.x, acc[3].x); acc[3].y = fmaf(wa.w, xd.y, acc[3].y);
    acc[3].z = fmaf(wa.w, xd.z, acc[3].z); acc[3].w = fmaf(wa.w, xd.w, acc[3].w);
    acc[4].x = fmaf(wb.x, xd.x, acc[4].x); acc[4].y = fmaf(wb.x, xd.y, acc[4].y);
    acc[4].z = fmaf(wb.x, xd.z, acc[4].z); acc[4].w = fmaf(wb.x, xd.w, acc[4].w);
    acc[5].x = fmaf(wb.y, xd.x, acc[5].x); acc[5].y = fmaf(wb.y, xd.y, acc[5].y);
    acc[5].z = fmaf(wb.y, xd.z, acc[5].z); acc[5].w = fmaf(wb.y, xd.w, acc[5].w);
    acc[6].x = fmaf(wb.z, xd.x, acc[6].x); acc[6].y = fmaf(wb.z, xd.y, acc[6].y);
    acc[6].z = fmaf(wb.z, xd.z, acc[6].z); acc[6].w = fmaf(wb.z, xd.w, acc[6].w);
    acc[7].x = fmaf(wb.w, xd.x, acc[7].x); acc[7].y = fmaf(wb.w, xd.y, acc[7].y);
    acc[7].z = fmaf(wb.w, xd.z, acc[7].z); acc[7].w = fmaf(wb.w, xd.w, acc[7].w);
}

// One warp per node. Edge list fetched 32-at-a-time (coalesced) and
// broadcast via shuffle -> no dependent perm chain. x/w pipeline depth 2.
__global__ __launch_bounds__(256) void node_kernel() {
    int warp = threadIdx.x >> 5;
    int lane = threadIdx.x & 31;
    int n = blockIdx.x * 8 + warp;
    if (n >= NN) return;

    int deg = g_cnt[n];
    int off = g_off[n];
    const float4* gx4 = (const float4*)g_x;
    const float4* gw4 = (const float4*)g_w;

    float4 acc[8];
    #pragma unroll
    for (int k = 0; k < 8; k++) acc[k] = make_float4(0.f, 0.f, 0.f, 0.f);

    for (int base = 0; base < deg; base += 32) {
        int cnt = min(32, deg - base);
        int pe = g_perm[off + base + ((lane < cnt) ? lane : (cnt - 1))];

        int eA = __shfl_sync(0xffffffffu, pe, 0);
        int iB = (cnt > 1) ? 1 : 0;
        int eB = __shfl_sync(0xffffffffu, pe, iB);
        float4 xA = gx4[(size_t)eA * 32 + lane];
        float4 waA = gw4[eA * 2], wbA = gw4[eA * 2 + 1];
        float4 xB = gx4[(size_t)eB * 32 + lane];
        float4 waB = gw4[eB * 2], wbB = gw4[eB * 2 + 1];

        for (int i = 0; i < cnt; i++) {
            int inx = (i + 2 < cnt) ? (i + 2) : (cnt - 1);
            int eC = __shfl_sync(0xffffffffu, pe, inx);
            float4 xC = gx4[(size_t)eC * 32 + lane];
            float4 waC = gw4[eC * 2], wbC = gw4[eC * 2 + 1];

            fma8(acc, xA, waA, wbA);

            xA = xB; waA = waB; wbA = wbB;
            xB = xC; waB = waC; wbB = wbC;
        }
    }

    // per-head 1/denom, applied once
    const float4* dn4 = (const float4*)(g_denom + n * KK);
    float4 d0 = dn4[0], d1 = dn4[1];
    float inv[8];
    inv[0] = (deg > 0) ? __frcp_rn(d0.x) : 0.f;
    inv[1] = (deg > 0) ? __frcp_rn(d0.y) : 0.f;
    inv[2] = (deg > 0) ? __frcp_rn(d0.z) : 0.f;
    inv[3] = (deg > 0) ? __frcp_rn(d0.w) : 0.f;
    inv[4] = (deg > 0) ? __frcp_rn(d1.x) : 0.f;
    inv[5] = (deg > 0) ? __frcp_rn(d1.y) : 0.f;
    inv[6] = (deg > 0) ? __frcp_rn(d1.z) : 0.f;
    inv[7] = (deg > 0) ? __frcp_rn(d1.w) : 0.f;

    float4* gy4 = (float4*)g_y;
    #pragma unroll
    for (int k = 0; k < 8; k++) {
        float4 o;
        o.x = acc[k].x * inv[k];
        o.y = acc[k].y * inv[k];
        o.z = acc[k].z * inv[k];
        o.w = acc[k].w * inv[k];
        gy4[(size_t)n * 256 + k * 32 + lane] = o;
    }

    __syncwarp();   // all lanes finished reading g_cnt/g_denom
    if (lane == 0) g_cnt[n] = 0;
    if (lane < KK) g_denom[n * KK + lane] = 0.f;
}

// ---------------- block-diagonal GEMM with packed f32x2 FMA ----------------
// out[n,k,:] = y[n,k,:] @ W_k.  Tile 128(n) x 64(h), BK=32, thread 8x4.
// As stored transposed (As[d][row]) so row-pairs load as 64-bit packed
// operands for fma.rn.f32x2 (2 MACs per issue slot). Bitwise identical to
// scalar FFMA (same rounding).
__global__ __launch_bounds__(256) void out_kernel(const float* __restrict__ W_enc,
                                                  float* __restrict__ out) {
    __shared__ float As[32][130];   // [d][row], 130 pad: 8B-aligned rows, spread banks
    __shared__ float Ws[32][65];
    int k = blockIdx.y;
    int n0 = blockIdx.x * 128;
    int tid = threadIdx.x;
    int tx = tid & 15, ty = tid >> 4;
    int ty8 = ty * 8, tx4 = tx * 4;

    ull c[4][4];                    // [row-pair][cc], each holds rows (2j, 2j+1)
    #pragma unroll
    for (int j = 0; j < 4; j++)
        #pragma unroll
        for (int cc = 0; cc < 4; cc++) c[j][cc] = 0ull;

    for (int kk = 0; kk < DD; kk += 32) {
        #pragma unroll
        for (int p = 0; p < 16; p++) {
            int q = tid + 256 * p;
            int row = q >> 5, d = q & 31;
            int n = n0 + row;
            As[d][row] = (n < NN) ? g_y[(size_t)n * (KK * DD) + k * DD + kk + d] : 0.f;
        }
        #pragma unroll
        for (int p = 0; p < 8; p++) {
            int q = tid + 256 * p;
            int d = q >> 6, h = q & 63;
            Ws[d][h] = W_enc[(size_t)(kk + d) * KHD + k * HH + h];
        }
        __syncthreads();
        #pragma unroll
        for (int d = 0; d < 32; d++) {
            ull a[4];
            a[0] = *(const ull*)&As[d][ty8];
            a[1] = *(const ull*)&As[d][ty8 + 2];
            a[2] = *(const ull*)&As[d][ty8 + 4];
            a[3] = *(const ull*)&As[d][ty8 + 6];
            #pragma unroll
            for (int cc = 0; cc < 4; cc++) {
                ull bb;
                DUP2(bb, Ws[d][tx4 + cc]);
                FMA2(c[0][cc], a[0], bb, c[0][cc]);
                FMA2(c[1][cc], a[1], bb, c[1][cc]);
                FMA2(c[2][cc], a[2], bb, c[2][cc]);
                FMA2(c[3][cc], a[3], bb, c[3][cc]);
            }
        }
        __syncthreads();
    }
    #pragma unroll
    for (int j = 0; j < 4; j++) {
        int r0 = n0 + ty8 + 2 * j;
        #pragma unroll
        for (int cc = 0; cc < 4; cc++) {
            unsigned int lo, hi;
            asm("mov.b64 {%0, %1}, %2;" : "=r"(lo), "=r"(hi) : "l"(c[j][cc]));
            if (r0 < NN)
                out[(size_t)r0 * KHD + k * HH + tx4 + cc] = __uint_as_float(lo);
            if (r0 + 1 < NN)
                out[(size_t)(r0 + 1) * KHD + k * HH + tx4 + cc] = __uint_as_float(hi);
        }
    }
}

// ---------------- launch ----------------------------------------------------
// edge_kernel sits at my launch index 3 -> it is the one ncu captures.
extern "C" void kernel_launch(void* const* d_in, const int* in_sizes, int n_in,
                              void* d_out, int out_size) {
    const float* node_feat = (const float*)d_in[0]; // (N,128)
    const float* edge_feat = (const float*)d_in[1]; // (E,3,128)
    const float* W_enc     = (const float*)d_in[2]; // (128,512)
    const float* attn_l    = (const float*)d_in[3]; // (1,8,64)
    const float* W_r       = (const float*)d_in[4]; // (8,128)
    const int*   dst       = (const int*)d_in[5];   // (E,)
    float* out = (float*)d_out;                     // (N,8,64)

    v_kernel<<<1, 1024>>>(W_enc, attn_l);                           // 0
    er_count_kernel<<<(NN + 7) / 8, 256>>>(node_feat, W_r, dst);    // 1
    scan_kernel<<<1, 1024>>>();                                     // 2
    edge_kernel<<<1480, 128>>>((const float4*)edge_feat, dst);      // 3  <- profiled
    fill_kernel<<<(EE + 255) / 256, 256>>>(dst);                    // 4
    node_kernel<<<(NN + 7) / 8, 256>>>();                           // 5
    out_kernel<<<dim3((NN + 127) / 128, 8), 256>>>(W_enc, out);     // 6
}

// round 7
// speedup vs baseline: 1.1496x; 1.1496x over previous
#include <cuda_runtime.h>

// Problem constants (fixed by the dataset)
#define NN 20000
#define EE 320000
#define DD 128
#define KK 8
#define HH 64
#define KHD 512   // K*H

typedef unsigned long long ull;
// packed fp32x2 helpers (sm_103a; PTX-only forms)
#define DUP2(o, f)  asm("mov.b64 %0, {%1, %1};" : "=l"(o) : "r"(__float_as_uint(f)))
#define FMA2(d, a, b, c) asm("fma.rn.f32x2 %0, %1, %2, %3;" : "=l"(d) : "l"(a), "l"(b), "l"(c))

// ---------------- scratch (__device__ globals; no allocations) -------------
// g_cnt and g_denom are zeroed at module load and re-zeroed at the END of
// node_kernel each run, so every graph replay starts from a clean state.
__device__ float g_x[(size_t)EE * DD];      // mean edge features (E,128)
__device__ float g_w[EE * KK];              // exp(leakyrelu(logit))
__device__ float g_er[NN * KK];             // node_feat @ W_r^T
__device__ float g_v[DD * KK];              // W_enc folded with attn_l
__device__ float g_denom[NN * KK];          // softmax denominators
__device__ float g_y[(size_t)NN * KK * DD]; // per-node weighted x sums (N,8,128)
__device__ int   g_cnt[NN];
__device__ int   g_off[NN];
__device__ int   g_cur[NN];
__device__ int   g_perm[EE];

// ---------------- CSR scan + fill ------------------------------------------
// single-block exclusive scan over 20000 counts (1024 threads x 20 chunk)
__global__ void scan_kernel() {
    __shared__ int s[1024];
    const int CH = 20;
    int tid = threadIdx.x;
    int start = tid * CH;
    int lsum = 0;
    for (int i = 0; i < CH; i++) {
        int idx = start + i;
        if (idx < NN) lsum += g_cnt[idx];
    }
    s[tid] = lsum;
    __syncthreads();
    for (int o = 1; o < 1024; o <<= 1) {
        int v = (tid >= o) ? s[tid - o] : 0;
        __syncthreads();
        s[tid] += v;
        __syncthreads();
    }
    int run = s[tid] - lsum;
    for (int i = 0; i < CH; i++) {
        int idx = start + i;
        if (idx < NN) {
            g_off[idx] = run;
            g_cur[idx] = run;
            run += g_cnt[idx];
        }
    }
}

__global__ void fill_kernel(const int* __restrict__ dst) {
    int e = blockIdx.x * blockDim.x + threadIdx.x;
    if (e < EE) {
        int pos = atomicAdd(&g_cur[dst[e]], 1);
        g_perm[pos] = e;
    }
}

// ---------------- small precomputes ---------------------------------------
// v[d,k] = sum_h W_enc[d, k*H+h] * attn_l[k,h]
__global__ void v_kernel(const float* __restrict__ W_enc,
                         const float* __restrict__ attn_l) {
    int i = threadIdx.x;          // 1024 threads = 128*8
    int d = i >> 3, k = i & 7;
    float s = 0.f;
    #pragma unroll 8
    for (int h = 0; h < HH; h++)
        s += W_enc[(size_t)d * KHD + k * HH + h] * attn_l[k * HH + h];
    g_v[d * KK + k] = s;
}

// fused: degree count (thread-per-edge) + er[n,k] (warp-per-node)
__global__ void er_count_kernel(const float* __restrict__ nf,
                                const float* __restrict__ W_r,
                                const int* __restrict__ dst) {
    int gtid = blockIdx.x * blockDim.x + threadIdx.x;
    if (gtid < EE) atomicAdd(&g_cnt[dst[gtid]], 1);

    int w = threadIdx.x >> 5;
    int lane = threadIdx.x & 31;
    int n = blockIdx.x * 8 + w;
    if (n >= NN) return;
    const float* row = nf + (size_t)n * DD;
    float a0 = row[lane], a1 = row[lane + 32], a2 = row[lane + 64], a3 = row[lane + 96];
    #pragma unroll
    for (int k = 0; k < KK; k++) {
        const float* wr = W_r + k * DD;
        float v = a0 * wr[lane] + a1 * wr[lane + 32] + a2 * wr[lane + 64] + a3 * wr[lane + 96];
        #pragma unroll
        for (int o = 16; o > 0; o >>= 1) v += __shfl_xor_sync(0xffffffffu, v, o);
        if (lane == 0) g_er[n * KK + k] = v;
    }
}

// ---------------- edge pass (warp-per-edge, float4, reg v, 2-deep pipe) ----
__global__ __launch_bounds__(128) void edge_kernel(const float4* __restrict__ ef4,
                                                   const int* __restrict__ dst) {
    int lane = threadIdx.x & 31;
    int gw = (blockIdx.x * blockDim.x + threadIdx.x) >> 5;
    int nw = (gridDim.x * blockDim.x) >> 5;

    const float4* gv4 = (const float4*)g_v;
    float4 vv0[4], vv1[4];
    #pragma unroll
    for (int dd = 0; dd < 4; dd++) {
        vv0[dd] = gv4[(4 * lane + dd) * 2 + 0];
        vv1[dd] = gv4[(4 * lane + dd) * 2 + 1];
    }
    int b4 = (lane >> 4) & 1, b3 = (lane >> 3) & 1, b2 = (lane >> 2) & 1;
    int myk = b4 * 4 + b3 * 2 + b2;
    float4* gx4 = (float4*)g_x;
    const float inv3 = 1.0f / 3.0f;

    if (gw >= EE) return;
    const float4* base = ef4 + (size_t)gw * 96;
    float4 c0 = base[lane];
    float4 c1 = base[lane + 32];
    float4 c2 = base[lane + 64];
    int cnd = dst[gw];

    for (int e = gw; e < EE; e += nw) {
        int e2 = e + nw;
        int ep = (e2 < EE) ? e2 : e;
        const float4* nbase = ef4 + (size_t)ep * 96;
        float4 n0 = nbase[lane];
        float4 n1 = nbase[lane + 32];
        float4 n2 = nbase[lane + 64];
        int nnd = dst[ep];

        float4 x;
        x.x = (c0.x + c1.x + c2.x) * inv3;
        x.y = (c0.y + c1.y + c2.y) * inv3;
        x.z = (c0.z + c1.z + c2.z) * inv3;
        x.w = (c0.w + c1.w + c2.w) * inv3;
        gx4[(size_t)e * 32 + lane] = x;

        float a[8];
        a[0] = x.x * vv0[0].x + x.y * vv0[1].x + x.z * vv0[2].x + x.w * vv0[3].x;
        a[1] = x.x * vv0[0].y + x.y * vv0[1].y + x.z * vv0[2].y + x.w * vv0[3].y;
        a[2] = x.x * vv0[0].z + x.y * vv0[1].z + x.z * vv0[2].z + x.w * vv0[3].z;
        a[3] = x.x * vv0[0].w + x.y * vv0[1].w + x.z * vv0[2].w + x.w * vv0[3].w;
        a[4] = x.x * vv1[0].x + x.y * vv1[1].x + x.z * vv1[2].x + x.w * vv1[3].x;
        a[5] = x.x * vv1[0].y + x.y * vv1[1].y + x.z * vv1[2].y + x.w * vv1[3].y;
        a[6] = x.x * vv1[0].z + x.y * vv1[1].z + x.z * vv1[2].z + x.w * vv1[3].z;
        a[7] = x.x * vv1[0].w + x.y * vv1[1].w + x.z * vv1[2].w + x.w * vv1[3].w;

        #pragma unroll
        for (int j = 0; j < 4; j++) {
            float keep = b4 ? a[j + 4] : a[j];
            float send = b4 ? a[j] : a[j + 4];
            a[j] = keep + __shfl_xor_sync(0xffffffffu, send, 16);
        }
        #pragma unroll
        for (int j = 0; j < 2; j++) {
            float keep = b3 ? a[j + 2] : a[j];
            float send = b3 ? a[j] : a[j + 2];
            a[j] = keep + __shfl_xor_sync(0xffffffffu, send, 8);
        }
        {
            float keep = b2 ? a[1] : a[0];
            float send = b2 ? a[0] : a[1];
            a[0] = keep + __shfl_xor_sync(0xffffffffu, send, 4);
        }
        a[0] += __shfl_xor_sync(0xffffffffu, a[0], 2);
        a[0] += __shfl_xor_sync(0xffffffffu, a[0], 1);

        if ((lane & 3) == 0) {
            float z = a[0] + g_er[cnd * KK + myk];
            z = (z > 0.f) ? z : 0.01f * z;            // leaky relu
            float wv = __expf(z);                     // shift-free softmax weight
            g_w[e * KK + myk] = wv;
            atomicAdd(&g_denom[cnd * KK + myk], wv);
        }

        c0 = n0; c1 = n1; c2 = n2; cnd = nnd;
    }
}

// ---------------- per-node weighted x aggregation (warp-per-NODE) ----------
// R4 version (proven fast): one warp per node; lane owns dims 4l..4l+3; all
// 8 heads accumulate in registers. Per edge: 1 LDG.128 + 2 uniform float4
// loads + 32 FFMA. Serial 2-deep prefetch, lean register footprint.
__global__ __launch_bounds__(256) void node_kernel() {
    int warp = threadIdx.x >> 5;
    int lane = threadIdx.x & 31;
    int n = blockIdx.x * 8 + warp;
    if (n >= NN) return;

    int deg = g_cnt[n];
    int off = g_off[n];
    const float4* gx4 = (const float4*)g_x;
    const float4* gw4 = (const float4*)g_w;

    float4 acc[8];
    #pragma unroll
    for (int k = 0; k < 8; k++) acc[k] = make_float4(0.f, 0.f, 0.f, 0.f);

    if (deg > 0) {
        int e = g_perm[off];
        float4 xd = gx4[(size_t)e * 32 + lane];
        float4 wa = gw4[e * 2], wb = gw4[e * 2 + 1];
        for (int i = 0; i < deg; i++) {
            int e2 = (i + 1 < deg) ? g_perm[off + i + 1] : e;
            float4 xn = gx4[(size_t)e2 * 32 + lane];
            float4 wan = gw4[e2 * 2], wbn = gw4[e2 * 2 + 1];

            acc[0].x = fmaf(wa.x, xd.x, acc[0].x);
            acc[0].y = fmaf(wa.x, xd.y, acc[0].y);
            acc[0].z = fmaf(wa.x, xd.z, acc[0].z);
            acc[0].w = fmaf(wa.x, xd.w, acc[0].w);
            acc[1].x = fmaf(wa.y, xd.x, acc[1].x);
            acc[1].y = fmaf(wa.y, xd.y, acc[1].y);
            acc[1].z = fmaf(wa.y, xd.z, acc[1].z);
            acc[1].w = fmaf(wa.y, xd.w, acc[1].w);
            acc[2].x = fmaf(wa.z, xd.x, acc[2].x);
            acc[2].y = fmaf(wa.z, xd.y, acc[2].y);
            acc[2].z = fmaf(wa.z, xd.z, acc[2].z);
            acc[2].w = fmaf(wa.z, xd.w, acc[2].w);
            acc[3].x = fmaf(wa.w, xd.x, acc[3].x);
            acc[3].y = fmaf(wa.w, xd.y, acc[3].y);
            acc[3].z = fmaf(wa.w, xd.z, acc[3].z);
            acc[3].w = fmaf(wa.w, xd.w, acc[3].w);
            acc[4].x = fmaf(wb.x, xd.x, acc[4].x);
            acc[4].y = fmaf(wb.x, xd.y, acc[4].y);
            acc[4].z = fmaf(wb.x, xd.z, acc[4].z);
            acc[4].w = fmaf(wb.x, xd.w, acc[4].w);
            acc[5].x = fmaf(wb.y, xd.x, acc[5].x);
            acc[5].y = fmaf(wb.y, xd.y, acc[5].y);
            acc[5].z = fmaf(wb.y, xd.z, acc[5].z);
            acc[5].w = fmaf(wb.y, xd.w, acc[5].w);
            acc[6].x = fmaf(wb.z, xd.x, acc[6].x);
            acc[6].y = fmaf(wb.z, xd.y, acc[6].y);
            acc[6].z = fmaf(wb.z, xd.z, acc[6].z);
            acc[6].w = fmaf(wb.z, xd.w, acc[6].w);
            acc[7].x = fmaf(wb.w, xd.x, acc[7].x);
            acc[7].y = fmaf(wb.w, xd.y, acc[7].y);
            acc[7].z = fmaf(wb.w, xd.z, acc[7].z);
            acc[7].w = fmaf(wb.w, xd.w, acc[7].w);

            xd = xn; wa = wan; wb = wbn;
        }
    }

    // per-head 1/denom, applied once
    const float4* dn4 = (const float4*)(g_denom + n * KK);
    float4 d0 = dn4[0], d1 = dn4[1];
    float inv[8];
    inv[0] = (deg > 0) ? __frcp_rn(d0.x) : 0.f;
    inv[1] = (deg > 0) ? __frcp_rn(d0.y) : 0.f;
    inv[2] = (deg > 0) ? __frcp_rn(d0.z) : 0.f;
    inv[3] = (deg > 0) ? __frcp_rn(d0.w) : 0.f;
    inv[4] = (deg > 0) ? __frcp_rn(d1.x) : 0.f;
    inv[5] = (deg > 0) ? __frcp_rn(d1.y) : 0.f;
    inv[6] = (deg > 0) ? __frcp_rn(d1.z) : 0.f;
    inv[7] = (deg > 0) ? __frcp_rn(d1.w) : 0.f;

    float4* gy4 = (float4*)g_y;
    #pragma unroll
    for (int k = 0; k < 8; k++) {
        float4 o;
        o.x = acc[k].x * inv[k];
        o.y = acc[k].y * inv[k];
        o.z = acc[k].z * inv[k];
        o.w = acc[k].w * inv[k];
        gy4[(size_t)n * 256 + k * 32 + lane] = o;
    }

    __syncwarp();   // all lanes finished reading g_cnt/g_denom
    if (lane == 0) g_cnt[n] = 0;
    if (lane < KK) g_denom[n * KK + lane] = 0.f;
}

// ---------------- block-diagonal GEMM with packed f32x2 FMA ----------------
// out[n,k,:] = y[n,k,:] @ W_k.  Tile 128(n) x 64(h), BK=32, thread 8x4.
// As stored transposed (As[d][row]) so row-pairs load as 64-bit packed
// operands for fma.rn.f32x2 (2 MACs per issue slot). Bitwise identical to
// scalar FFMA (same rounding).
__global__ __launch_bounds__(256) void out_kernel(const float* __restrict__ W_enc,
                                                  float* __restrict__ out) {
    __shared__ float As[32][130];   // [d][row], 130 pad: 8B-aligned rows
    __shared__ float Ws[32][65];
    int k = blockIdx.y;
    int n0 = blockIdx.x * 128;
    int tid = threadIdx.x;
    int tx = tid & 15, ty = tid >> 4;
    int ty8 = ty * 8, tx4 = tx * 4;

    ull c[4][4];                    // [row-pair][cc], each holds rows (2j, 2j+1)
    #pragma unroll
    for (int j = 0; j < 4; j++)
        #pragma unroll
        for (int cc = 0; cc < 4; cc++) c[j][cc] = 0ull;

    for (int kk = 0; kk < DD; kk += 32) {
        #pragma unroll
        for (int p = 0; p < 16; p++) {
            int q = tid + 256 * p;
            int row = q >> 5, d = q & 31;
            int n = n0 + row;
            As[d][row] = (n < NN) ? g_y[(size_t)n * (KK * DD) + k * DD + kk + d] : 0.f;
        }
        #pragma unroll
        for (int p = 0; p < 8; p++) {
            int q = tid + 256 * p;
            int d = q >> 6, h = q & 63;
            Ws[d][h] = W_enc[(size_t)(kk + d) * KHD + k * HH + h];
        }
        __syncthreads();
        #pragma unroll
        for (int d = 0; d < 32; d++) {
            ull a[4];
            a[0] = *(const ull*)&As[d][ty8];
            a[1] = *(const ull*)&As[d][ty8 + 2];
            a[2] = *(const ull*)&As[d][ty8 + 4];
            a[3] = *(const ull*)&As[d][ty8 + 6];
            #pragma unroll
            for (int cc = 0; cc < 4; cc++) {
                ull bb;
                DUP2(bb, Ws[d][tx4 + cc]);
                FMA2(c[0][cc], a[0], bb, c[0][cc]);
                FMA2(c[1][cc], a[1], bb, c[1][cc]);
                FMA2(c[2][cc], a[2], bb, c[2][cc]);
                FMA2(c[3][cc], a[3], bb, c[3][cc]);
            }
        }
        __syncthreads();
    }
    #pragma unroll
    for (int j = 0; j < 4; j++) {
        int r0 = n0 + ty8 + 2 * j;
        #pragma unroll
        for (int cc = 0; cc < 4; cc++) {
            unsigned int lo, hi;
            asm("mov.b64 {%0, %1}, %2;" : "=r"(lo), "=r"(hi) : "l"(c[j][cc]));
            if (r0 < NN)
                out[(size_t)r0 * KHD + k * HH + tx4 + cc] = __uint_as_float(lo);
            if (r0 + 1 < NN)
                out[(size_t)(r0 + 1) * KHD + k * HH + tx4 + cc] = __uint_as_float(hi);
        }
    }
}

// ---------------- launch ----------------------------------------------------
// edge_kernel stays at my launch index 3 -> it is the ncu control reading.
extern "C" void kernel_launch(void* const* d_in, const int* in_sizes, int n_in,
                              void* d_out, int out_size) {
    const float* node_feat = (const float*)d_in[0]; // (N,128)
    const float* edge_feat = (const float*)d_in[1]; // (E,3,128)
    const float* W_enc     = (const float*)d_in[2]; // (128,512)
    const float* attn_l    = (const float*)d_in[3]; // (1,8,64)
    const float* W_r       = (const float*)d_in[4]; // (8,128)
    const int*   dst       = (const int*)d_in[5];   // (E,)
    float* out = (float*)d_out;                     // (N,8,64)

    v_kernel<<<1, 1024>>>(W_enc, attn_l);                           // 0
    er_count_kernel<<<(NN + 7) / 8, 256>>>(node_feat, W_r, dst);    // 1
    scan_kernel<<<1, 1024>>>();                                     // 2
    edge_kernel<<<1480, 128>>>((const float4*)edge_feat, dst);      // 3  <- profiled
    fill_kernel<<<(EE + 255) / 256, 256>>>(dst);                    // 4
    node_kernel<<<(NN + 7) / 8, 256>>>();                           // 5
    out_kernel<<<dim3((NN + 127) / 128, 8), 256>>>(W_enc, out);     // 6
}

// round 9
// speedup vs baseline: 1.1653x; 1.0137x over previous
#include <cuda_runtime.h>

// Problem constants (fixed by the dataset)
#define NN 20000
#define EE 320000
#define DD 128
#define KK 8
#define HH 64
#define KHD 512   // K*H

typedef unsigned long long ull;
// packed fp32x2 helpers (sm_103a; PTX-only forms)
#define DUP2(o, f)  asm("mov.b64 %0, {%1, %1};" : "=l"(o) : "r"(__float_as_uint(f)))
#define FMA2(d, a, b, c) asm("fma.rn.f32x2 %0, %1, %2, %3;" : "=l"(d) : "l"(a), "l"(b), "l"(c))
#define MUL2(d, a, b) asm("mul.rn.f32x2 %0, %1, %2;" : "=l"(d) : "l"(a), "l"(b))

// ---------------- scratch (__device__ globals; no allocations) -------------
// g_cnt and g_denom are zeroed at module load and re-zeroed at the END of
// node_kernel each run, so every graph replay starts from a clean state.
__device__ float g_x[(size_t)EE * DD];      // mean edge features (E,128)
__device__ float g_w[EE * KK];              // exp(leakyrelu(logit))
__device__ float g_er[NN * KK];             // node_feat @ W_r^T
__device__ float g_v[DD * KK];              // W_enc folded with attn_l
__device__ float g_denom[NN * KK];          // softmax denominators
__device__ float g_y[(size_t)NN * KK * DD]; // per-node weighted x sums (N,8,128)
__device__ int   g_cnt[NN];
__device__ int   g_off[NN];
__device__ int   g_cur[NN];
__device__ int   g_perm[EE];

// ---------------- CSR scan + fill ------------------------------------------
// single-block exclusive scan over 20000 counts (1024 threads x 20 chunk)
__global__ void scan_kernel() {
    __shared__ int s[1024];
    const int CH = 20;
    int tid = threadIdx.x;
    int start = tid * CH;
    int lsum = 0;
    for (int i = 0; i < CH; i++) {
        int idx = start + i;
        if (idx < NN) lsum += g_cnt[idx];
    }
    s[tid] = lsum;
    __syncthreads();
    for (int o = 1; o < 1024; o <<= 1) {
        int v = (tid >= o) ? s[tid - o] : 0;
        __syncthreads();
        s[tid] += v;
        __syncthreads();
    }
    int run = s[tid] - lsum;
    for (int i = 0; i < CH; i++) {
        int idx = start + i;
        if (idx < NN) {
            g_off[idx] = run;
            g_cur[idx] = run;
            run += g_cnt[idx];
        }
    }
}

__global__ void fill_kernel(const int* __restrict__ dst) {
    int e = blockIdx.x * blockDim.x + threadIdx.x;
    if (e < EE) {
        int pos = atomicAdd(&g_cur[dst[e]], 1);
        g_perm[pos] = e;
    }
}

// ---------------- fused precompute: count + er + v -------------------------
__global__ void er_count_kernel(const float* __restrict__ nf,
                                const float* __restrict__ W_r,
                                const int* __restrict__ dst,
                                const float* __restrict__ W_enc,
                                const float* __restrict__ attn_l) {
    int gtid = blockIdx.x * blockDim.x + threadIdx.x;
    if (gtid < EE) atomicAdd(&g_cnt[dst[gtid]], 1);

    if (blockIdx.x == 0) {
        // 256 threads x 4 entries = 1024 = 128*8 entries of v
        for (int j = 0; j < 4; j++) {
            int i = threadIdx.x * 4 + j;
            int d = i >> 3, k = i & 7;
            float s = 0.f;
            #pragma unroll 8
            for (int h = 0; h < HH; h++)
                s += W_enc[(size_t)d * KHD + k * HH + h] * attn_l[k * HH + h];
            g_v[d * KK + k] = s;
        }
    }

    int w = threadIdx.x >> 5;
    int lane = threadIdx.x & 31;
    int n = blockIdx.x * 8 + w;
    if (n >= NN) return;
    const float* row = nf + (size_t)n * DD;
    float a0 = row[lane], a1 = row[lane + 32], a2 = row[lane + 64], a3 = row[lane + 96];
    #pragma unroll
    for (int k = 0; k < KK; k++) {
        const float* wr = W_r + k * DD;
        float v = a0 * wr[lane] + a1 * wr[lane + 32] + a2 * wr[lane + 64] + a3 * wr[lane + 96];
        #pragma unroll
        for (int o = 16; o > 0; o >>= 1) v += __shfl_xor_sync(0xffffffffu, v, o);
        if (lane == 0) g_er[n * KK + k] = v;
    }
}

// ---------------- edge pass (warp-per-edge, one wave, ldcs, er prefetch) ---
// grid = 148 SM x 7 resident blocks = 1036 blocks -> EXACTLY one wave (no
// 43%-occupancy tail wave). __ldcs on the streamed edge_feat reads keeps L2
// for g_x. g_er gather prefetched one iteration ahead.
#define EDGE_GRID 1036
__global__ __launch_bounds__(128, 7) void edge_kernel(const float4* __restrict__ ef4,
                                                      const int* __restrict__ dst) {
    int lane = threadIdx.x & 31;
    int gw = (blockIdx.x * blockDim.x + threadIdx.x) >> 5;
    int nw = (gridDim.x * blockDim.x) >> 5;

    const float4* gv4 = (const float4*)g_v;
    float4 vv0[4], vv1[4];
    #pragma unroll
    for (int dd = 0; dd < 4; dd++) {
        vv0[dd] = gv4[(4 * lane + dd) * 2 + 0];
        vv1[dd] = gv4[(4 * lane + dd) * 2 + 1];
    }
    int b4 = (lane >> 4) & 1, b3 = (lane >> 3) & 1, b2 = (lane >> 2) & 1;
    int myk = b4 * 4 + b3 * 2 + b2;
    float4* gx4 = (float4*)g_x;
    const float inv3 = 1.0f / 3.0f;

    if (gw >= EE) return;
    const float4* base = ef4 + (size_t)gw * 96;
    float4 c0 = __ldcs(base + lane);
    float4 c1 = __ldcs(base + lane + 32);
    float4 c2 = __ldcs(base + lane + 64);
    int cnd = dst[gw];
    float cer = g_er[cnd * KK + myk];

    for (int e = gw; e < EE; e += nw) {
        int e2 = e + nw;
        int ep = (e2 < EE) ? e2 : e;
        const float4* nbase = ef4 + (size_t)ep * 96;
        float4 n0 = __ldcs(nbase + lane);
        float4 n1 = __ldcs(nbase + lane + 32);
        float4 n2 = __ldcs(nbase + lane + 64);
        int nnd = dst[ep];
        float ner = g_er[nnd * KK + myk];

        float4 x;
        x.x = (c0.x + c1.x + c2.x) * inv3;
        x.y = (c0.y + c1.y + c2.y) * inv3;
        x.z = (c0.z + c1.z + c2.z) * inv3;
        x.w = (c0.w + c1.w + c2.w) * inv3;
        gx4[(size_t)e * 32 + lane] = x;

        float a[8];
        a[0] = x.x * vv0[0].x + x.y * vv0[1].x + x.z * vv0[2].x + x.w * vv0[3].x;
        a[1] = x.x * vv0[0].y + x.y * vv0[1].y + x.z * vv0[2].y + x.w * vv0[3].y;
        a[2] = x.x * vv0[0].z + x.y * vv0[1].z + x.z * vv0[2].z + x.w * vv0[3].z;
        a[3] = x.x * vv0[0].w + x.y * vv0[1].w + x.z * vv0[2].w + x.w * vv0[3].w;
        a[4] = x.x * vv1[0].x + x.y * vv1[1].x + x.z * vv1[2].x + x.w * vv1[3].x;
        a[5] = x.x * vv1[0].y + x.y * vv1[1].y + x.z * vv1[2].y + x.w * vv1[3].y;
        a[6] = x.x * vv1[0].z + x.y * vv1[1].z + x.z * vv1[2].z + x.w * vv1[3].z;
        a[7] = x.x * vv1[0].w + x.y * vv1[1].w + x.z * vv1[2].w + x.w * vv1[3].w;

        #pragma unroll
        for (int j = 0; j < 4; j++) {
            float keep = b4 ? a[j + 4] : a[j];
            float send = b4 ? a[j] : a[j + 4];
            a[j] = keep + __shfl_xor_sync(0xffffffffu, send, 16);
        }
        #pragma unroll
        for (int j = 0; j < 2; j++) {
            float keep = b3 ? a[j + 2] : a[j];
            float send = b3 ? a[j] : a[j + 2];
            a[j] = keep + __shfl_xor_sync(0xffffffffu, send, 8);
        }
        {
            float keep = b2 ? a[1] : a[0];
            float send = b2 ? a[0] : a[1];
            a[0] = keep + __shfl_xor_sync(0xffffffffu, send, 4);
        }
        a[0] += __shfl_xor_sync(0xffffffffu, a[0], 2);
        a[0] += __shfl_xor_sync(0xffffffffu, a[0], 1);

        if ((lane & 3) == 0) {
            float z = a[0] + cer;
            z = (z > 0.f) ? z : 0.01f * z;            // leaky relu
            float wv = __expf(z);                     // shift-free softmax weight
            g_w[e * KK + myk] = wv;
            atomicAdd(&g_denom[cnd * KK + myk], wv);
        }

        c0 = n0; c1 = n1; c2 = n2; cnd = nnd; cer = ner;
    }
}

// ---------------- per-node weighted x aggregation (warp-per-NODE, f32x2) ---
// R4 structure with packed math. FIXED indexing: a ulonglong2 = 16 bytes =
// 4 floats, so an x-row (128 f) = 32 elems -> gx2[e*32 + lane]; a y-node
// (1024 f) = 256 elems, per-k 32 -> gy2[n*256 + k*32 + lane].
__global__ __launch_bounds__(256) void node_kernel() {
    int warp = threadIdx.x >> 5;
    int lane = threadIdx.x & 31;
    int n = blockIdx.x * 8 + warp;
    if (n >= NN) return;

    int deg = g_cnt[n];
    int off = g_off[n];
    const ulonglong2* gx2 = (const ulonglong2*)g_x;
    const float4* gw4 = (const float4*)g_w;

    ull acc[8][2];
    #pragma unroll
    for (int k = 0; k < 8; k++) { acc[k][0] = 0ull; acc[k][1] = 0ull; }

    if (deg > 0) {
        int e = g_perm[off];
        ulonglong2 xd = gx2[(size_t)e * 32 + lane];
        float4 wa = gw4[e * 2], wb = gw4[e * 2 + 1];
        for (int i = 0; i < deg; i++) {
            int e2 = (i + 1 < deg) ? g_perm[off + i + 1] : e;
            ulonglong2 xn = gx2[(size_t)e2 * 32 + lane];
            float4 wan = gw4[e2 * 2], wbn = gw4[e2 * 2 + 1];

            ull w2;
            DUP2(w2, wa.x); FMA2(acc[0][0], xd.x, w2, acc[0][0]); FMA2(acc[0][1], xd.y, w2, acc[0][1]);
            DUP2(w2, wa.y); FMA2(acc[1][0], xd.x, w2, acc[1][0]); FMA2(acc[1][1], xd.y, w2, acc[1][1]);
            DUP2(w2, wa.z); FMA2(acc[2][0], xd.x, w2, acc[2][0]); FMA2(acc[2][1], xd.y, w2, acc[2][1]);
            DUP2(w2, wa.w); FMA2(acc[3][0], xd.x, w2, acc[3][0]); FMA2(acc[3][1], xd.y, w2, acc[3][1]);
            DUP2(w2, wb.x); FMA2(acc[4][0], xd.x, w2, acc[4][0]); FMA2(acc[4][1], xd.y, w2, acc[4][1]);
            DUP2(w2, wb.y); FMA2(acc[5][0], xd.x, w2, acc[5][0]); FMA2(acc[5][1], xd.y, w2, acc[5][1]);
            DUP2(w2, wb.z); FMA2(acc[6][0], xd.x, w2, acc[6][0]); FMA2(acc[6][1], xd.y, w2, acc[6][1]);
            DUP2(w2, wb.w); FMA2(acc[7][0], xd.x, w2, acc[7][0]); FMA2(acc[7][1], xd.y, w2, acc[7][1]);

            xd = xn; wa = wan; wb = wbn;
        }
    }

    // per-head 1/denom, applied once (packed multiply)
    const float4* dn4 = (const float4*)(g_denom + n * KK);
    float4 d0 = dn4[0], d1 = dn4[1];
    float inv[8];
    inv[0] = (deg > 0) ? __frcp_rn(d0.x) : 0.f;
    inv[1] = (deg > 0) ? __frcp_rn(d0.y) : 0.f;
    inv[2] = (deg > 0) ? __frcp_rn(d0.z) : 0.f;
    inv[3] = (deg > 0) ? __frcp_rn(d0.w) : 0.f;
    inv[4] = (deg > 0) ? __frcp_rn(d1.x) : 0.f;
    inv[5] = (deg > 0) ? __frcp_rn(d1.y) : 0.f;
    inv[6] = (deg > 0) ? __frcp_rn(d1.z) : 0.f;
    inv[7] = (deg > 0) ? __frcp_rn(d1.w) : 0.f;

    ulonglong2* gy2 = (ulonglong2*)g_y;
    #pragma unroll
    for (int k = 0; k < 8; k++) {
        ull iv;
        DUP2(iv, inv[k]);
        ulonglong2 o;
        MUL2(o.x, acc[k][0], iv);
        MUL2(o.y, acc[k][1], iv);
        gy2[(size_t)n * 256 + k * 32 + lane] = o;
    }

    __syncwarp();   // all lanes finished reading g_cnt/g_denom
    if (lane == 0) g_cnt[n] = 0;
    if (lane < KK) g_denom[n * KK + lane] = 0.f;
}

// ---------------- block-diagonal GEMM with packed f32x2 FMA ----------------
// out[n,k,:] = y[n,k,:] @ W_k.  Tile 128(n) x 64(h), BK=32, thread 8x4.
__global__ __launch_bounds__(256) void out_kernel(const float* __restrict__ W_enc,
                                                  float* __restrict__ out) {
    __shared__ float As[32][130];   // [d][row], 130 pad: 8B-aligned rows
    __shared__ float Ws[32][65];
    int k = blockIdx.y;
    int n0 = blockIdx.x * 128;
    int tid = threadIdx.x;
    int tx = tid & 15, ty = tid >> 4;
    int ty8 = ty * 8, tx4 = tx * 4;

    ull c[4][4];                    // [row-pair][cc], each holds rows (2j, 2j+1)
    #pragma unroll
    for (int j = 0; j < 4; j++)
        #pragma unroll
        for (int cc = 0; cc < 4; cc++) c[j][cc] = 0ull;

    for (int kk = 0; kk < DD; kk += 32) {
        #pragma unroll
        for (int p = 0; p < 16; p++) {
            int q = tid + 256 * p;
            int row = q >> 5, d = q & 31;
            int n = n0 + row;
            As[d][row] = (n < NN) ? g_y[(size_t)n * (KK * DD) + k * DD + kk + d] : 0.f;
        }
        #pragma unroll
        for (int p = 0; p < 8; p++) {
            int q = tid + 256 * p;
            int d = q >> 6, h = q & 63;
            Ws[d][h] = W_enc[(size_t)(kk + d) * KHD + k * HH + h];
        }
        __syncthreads();
        #pragma unroll
        for (int d = 0; d < 32; d++) {
            ull a[4];
            a[0] = *(const ull*)&As[d][ty8];
            a[1] = *(const ull*)&As[d][ty8 + 2];
            a[2] = *(const ull*)&As[d][ty8 + 4];
            a[3] = *(const ull*)&As[d][ty8 + 6];
            #pragma unroll
            for (int cc = 0; cc < 4; cc++) {
                ull bb;
                DUP2(bb, Ws[d][tx4 + cc]);
                FMA2(c[0][cc], a[0], bb, c[0][cc]);
                FMA2(c[1][cc], a[1], bb, c[1][cc]);
                FMA2(c[2][cc], a[2], bb, c[2][cc]);
                FMA2(c[3][cc], a[3], bb, c[3][cc]);
            }
        }
        __syncthreads();
    }
    #pragma unroll
    for (int j = 0; j < 4; j++) {
        int r0 = n0 + ty8 + 2 * j;
        #pragma unroll
        for (int cc = 0; cc < 4; cc++) {
            unsigned int lo, hi;
            asm("mov.b64 {%0, %1}, %2;" : "=r"(lo), "=r"(hi) : "l"(c[j][cc]));
            if (r0 < NN)
                out[(size_t)r0 * KHD + k * HH + tx4 + cc] = __uint_as_float(lo);
            if (r0 + 1 < NN)
                out[(size_t)(r0 + 1) * KHD + k * HH + tx4 + cc] = __uint_as_float(hi);
        }
    }
}

// ---------------- launch ----------------------------------------------------
// edge_kernel stays at my launch index 3 -> it is the ncu control reading.
extern "C" void kernel_launch(void* const* d_in, const int* in_sizes, int n_in,
                              void* d_out, int out_size) {
    const float* node_feat = (const float*)d_in[0]; // (N,128)
    const float* edge_feat = (const float*)d_in[1]; // (E,3,128)
    const float* W_enc     = (const float*)d_in[2]; // (128,512)
    const float* attn_l    = (const float*)d_in[3]; // (1,8,64)
    const float* W_r       = (const float*)d_in[4]; // (8,128)
    const int*   dst       = (const int*)d_in[5];   // (E,)
    float* out = (float*)d_out;                     // (N,8,64)

    er_count_kernel<<<(NN + 7) / 8, 256>>>(node_feat, W_r, dst, W_enc, attn_l); // 0
    scan_kernel<<<1, 1024>>>();                                                 // 1
    fill_kernel<<<(EE + 255) / 256, 256>>>(dst);                                // 2
    edge_kernel<<<EDGE_GRID, 128>>>((const float4*)edge_feat, dst);             // 3  <- profiled
    node_kernel<<<(NN + 7) / 8, 256>>>();                                       // 4
    out_kernel<<<dim3((NN + 127) / 128, 8), 256>>>(W_enc, out);                 // 5
}

// round 11
// speedup vs baseline: 1.1687x; 1.0029x over previous
#include <cuda_runtime.h>

// Problem constants (fixed by the dataset)
#define NN 20000
#define EE 320000
#define DD 128
#define KK 8
#define HH 64
#define KHD 512   // K*H

typedef unsigned long long ull;
// packed fp32x2 helpers (sm_103a; PTX-only forms)
#define DUP2(o, f)  asm("mov.b64 %0, {%1, %1};" : "=l"(o) : "r"(__float_as_uint(f)))
#define FMA2(d, a, b, c) asm("fma.rn.f32x2 %0, %1, %2, %3;" : "=l"(d) : "l"(a), "l"(b), "l"(c))
#define MUL2(d, a, b) asm("mul.rn.f32x2 %0, %1, %2;" : "=l"(d) : "l"(a), "l"(b))

// ---------------- scratch (__device__ globals; no allocations) -------------
// g_cnt and g_denom are zeroed at module load and re-zeroed at the END of
// node_kernel each run, so every graph replay starts from a clean state.
__device__ float g_x[(size_t)EE * DD];      // mean edge features (E,128)
__device__ float g_w[EE * KK];              // exp(leakyrelu(logit))
__device__ float g_er[NN * KK];             // node_feat @ W_r^T
__device__ float g_v[DD * KK];              // W_enc folded with attn_l
__device__ float g_denom[NN * KK];          // softmax denominators
__device__ float g_y[(size_t)NN * KK * DD]; // per-node weighted x sums (N,8,128)
__device__ int   g_cnt[NN];
__device__ int   g_off[NN];
__device__ int   g_cur[NN];
__device__ int   g_perm[EE];

// ---------------- CSR scan -------------------------------------------------
// single-block exclusive scan over 20000 counts (1024 threads x 20 chunk)
__global__ void scan_kernel() {
    __shared__ int s[1024];
    const int CH = 20;
    int tid = threadIdx.x;
    int start = tid * CH;
    int lsum = 0;
    for (int i = 0; i < CH; i++) {
        int idx = start + i;
        if (idx < NN) lsum += g_cnt[idx];
    }
    s[tid] = lsum;
    __syncthreads();
    for (int o = 1; o < 1024; o <<= 1) {
        int v = (tid >= o) ? s[tid - o] : 0;
        __syncthreads();
        s[tid] += v;
        __syncthreads();
    }
    int run = s[tid] - lsum;
    for (int i = 0; i < CH; i++) {
        int idx = start + i;
        if (idx < NN) {
            g_off[idx] = run;
            g_cur[idx] = run;
            run += g_cnt[idx];
        }
    }
}

// ---------------- fused precompute: count + er + v -------------------------
__global__ void er_count_kernel(const float* __restrict__ nf,
                                const float* __restrict__ W_r,
                                const int* __restrict__ dst,
                                const float* __restrict__ W_enc,
                                const float* __restrict__ attn_l) {
    int gtid = blockIdx.x * blockDim.x + threadIdx.x;
    if (gtid < EE) atomicAdd(&g_cnt[dst[gtid]], 1);

    if (blockIdx.x == 0) {
        // 256 threads x 4 entries = 1024 = 128*8 entries of v
        for (int j = 0; j < 4; j++) {
            int i = threadIdx.x * 4 + j;
            int d = i >> 3, k = i & 7;
            float s = 0.f;
            #pragma unroll 8
            for (int h = 0; h < HH; h++)
                s += W_enc[(size_t)d * KHD + k * HH + h] * attn_l[k * HH + h];
            g_v[d * KK + k] = s;
        }
    }

    int w = threadIdx.x >> 5;
    int lane = threadIdx.x & 31;
    int n = blockIdx.x * 8 + w;
    if (n >= NN) return;
    const float* row = nf + (size_t)n * DD;
    float a0 = row[lane], a1 = row[lane + 32], a2 = row[lane + 64], a3 = row[lane + 96];
    #pragma unroll
    for (int k = 0; k < KK; k++) {
        const float* wr = W_r + k * DD;
        float v = a0 * wr[lane] + a1 * wr[lane + 32] + a2 * wr[lane + 64] + a3 * wr[lane + 96];
        #pragma unroll
        for (int o = 16; o > 0; o >>= 1) v += __shfl_xor_sync(0xffffffffu, v, o);
        if (lane == 0) g_er[n * KK + k] = v;
    }
}

// ---------------- edge pass (warp-per-edge, one wave, ldcs, fused fill) ----
// grid = 148 SM x 7 resident blocks = 1036 blocks -> exactly one wave.
// __ldcs on the streamed edge_feat reads. g_er gather prefetched one
// iteration ahead. NEW: CSR perm fill fused in (lane 0 per edge), removing
// the separate fill_kernel launch; g_cur was pre-set to g_off by scan.
#define EDGE_GRID 1036
__global__ __launch_bounds__(128, 7) void edge_kernel(const float4* __restrict__ ef4,
                                                      const int* __restrict__ dst) {
    int lane = threadIdx.x & 31;
    int gw = (blockIdx.x * blockDim.x + threadIdx.x) >> 5;
    int nw = (gridDim.x * blockDim.x) >> 5;

    const float4* gv4 = (const float4*)g_v;
    float4 vv0[4], vv1[4];
    #pragma unroll
    for (int dd = 0; dd < 4; dd++) {
        vv0[dd] = gv4[(4 * lane + dd) * 2 + 0];
        vv1[dd] = gv4[(4 * lane + dd) * 2 + 1];
    }
    int b4 = (lane >> 4) & 1, b3 = (lane >> 3) & 1, b2 = (lane >> 2) & 1;
    int myk = b4 * 4 + b3 * 2 + b2;
    float4* gx4 = (float4*)g_x;
    const float inv3 = 1.0f / 3.0f;

    if (gw >= EE) return;
    const float4* base = ef4 + (size_t)gw * 96;
    float4 c0 = __ldcs(base + lane);
    float4 c1 = __ldcs(base + lane + 32);
    float4 c2 = __ldcs(base + lane + 64);
    int cnd = dst[gw];
    float cer = g_er[cnd * KK + myk];

    for (int e = gw; e < EE; e += nw) {
        int e2 = e + nw;
        int ep = (e2 < EE) ? e2 : e;
        const float4* nbase = ef4 + (size_t)ep * 96;
        float4 n0 = __ldcs(nbase + lane);
        float4 n1 = __ldcs(nbase + lane + 32);
        float4 n2 = __ldcs(nbase + lane + 64);
        int nnd = dst[ep];
        float ner = g_er[nnd * KK + myk];

        // fused CSR fill: one lane per edge claims a slot
        if (lane == 0) {
            int pos = atomicAdd(&g_cur[cnd], 1);
            g_perm[pos] = e;
        }

        float4 x;
        x.x = (c0.x + c1.x + c2.x) * inv3;
        x.y = (c0.y + c1.y + c2.y) * inv3;
        x.z = (c0.z + c1.z + c2.z) * inv3;
        x.w = (c0.w + c1.w + c2.w) * inv3;
        gx4[(size_t)e * 32 + lane] = x;

        float a[8];
        a[0] = x.x * vv0[0].x + x.y * vv0[1].x + x.z * vv0[2].x + x.w * vv0[3].x;
        a[1] = x.x * vv0[0].y + x.y * vv0[1].y + x.z * vv0[2].y + x.w * vv0[3].y;
        a[2] = x.x * vv0[0].z + x.y * vv0[1].z + x.z * vv0[2].z + x.w * vv0[3].z;
        a[3] = x.x * vv0[0].w + x.y * vv0[1].w + x.z * vv0[2].w + x.w * vv0[3].w;
        a[4] = x.x * vv1[0].x + x.y * vv1[1].x + x.z * vv1[2].x + x.w * vv1[3].x;
        a[5] = x.x * vv1[0].y + x.y * vv1[1].y + x.z * vv1[2].y + x.w * vv1[3].y;
        a[6] = x.x * vv1[0].z + x.y * vv1[1].z + x.z * vv1[2].z + x.w * vv1[3].z;
        a[7] = x.x * vv1[0].w + x.y * vv1[1].w + x.z * vv1[2].w + x.w * vv1[3].w;

        #pragma unroll
        for (int j = 0; j < 4; j++) {
            float keep = b4 ? a[j + 4] : a[j];
            float send = b4 ? a[j] : a[j + 4];
            a[j] = keep + __shfl_xor_sync(0xffffffffu, send, 16);
        }
        #pragma unroll
        for (int j = 0; j < 2; j++) {
            float keep = b3 ? a[j + 2] : a[j];
            float send = b3 ? a[j] : a[j + 2];
            a[j] = keep + __shfl_xor_sync(0xffffffffu, send, 8);
        }
        {
            float keep = b2 ? a[1] : a[0];
            float send = b2 ? a[0] : a[1];
            a[0] = keep + __shfl_xor_sync(0xffffffffu, send, 4);
        }
        a[0] += __shfl_xor_sync(0xffffffffu, a[0], 2);
        a[0] += __shfl_xor_sync(0xffffffffu, a[0], 1);

        if ((lane & 3) == 0) {
            float z = a[0] + cer;
            z = (z > 0.f) ? z : 0.01f * z;            // leaky relu
            float wv = __expf(z);                     // shift-free softmax weight
            g_w[e * KK + myk] = wv;
            atomicAdd(&g_denom[cnd * KK + myk], wv);
        }

        c0 = n0; c1 = n1; c2 = n2; cnd = nnd; cer = ner;
    }
}

// ---------------- per-node weighted x aggregation (warp-per-NODE, f32x2) ---
// (unchanged from R9 — lands in the PROFILED slot this round)
__global__ __launch_bounds__(256) void node_kernel() {
    int warp = threadIdx.x >> 5;
    int lane = threadIdx.x & 31;
    int n = blockIdx.x * 8 + warp;
    if (n >= NN) return;

    int deg = g_cnt[n];
    int off = g_off[n];
    const ulonglong2* gx2 = (const ulonglong2*)g_x;
    const float4* gw4 = (const float4*)g_w;

    ull acc[8][2];
    #pragma unroll
    for (int k = 0; k < 8; k++) { acc[k][0] = 0ull; acc[k][1] = 0ull; }

    if (deg > 0) {
        int e = g_perm[off];
        ulonglong2 xd = gx2[(size_t)e * 32 + lane];
        float4 wa = gw4[e * 2], wb = gw4[e * 2 + 1];
        for (int i = 0; i < deg; i++) {
            int e2 = (i + 1 < deg) ? g_perm[off + i + 1] : e;
            ulonglong2 xn = gx2[(size_t)e2 * 32 + lane];
            float4 wan = gw4[e2 * 2], wbn = gw4[e2 * 2 + 1];

            ull w2;
            DUP2(w2, wa.x); FMA2(acc[0][0], xd.x, w2, acc[0][0]); FMA2(acc[0][1], xd.y, w2, acc[0][1]);
            DUP2(w2, wa.y); FMA2(acc[1][0], xd.x, w2, acc[1][0]); FMA2(acc[1][1], xd.y, w2, acc[1][1]);
            DUP2(w2, wa.z); FMA2(acc[2][0], xd.x, w2, acc[2][0]); FMA2(acc[2][1], xd.y, w2, acc[2][1]);
            DUP2(w2, wa.w); FMA2(acc[3][0], xd.x, w2, acc[3][0]); FMA2(acc[3][1], xd.y, w2, acc[3][1]);
            DUP2(w2, wb.x); FMA2(acc[4][0], xd.x, w2, acc[4][0]); FMA2(acc[4][1], xd.y, w2, acc[4][1]);
            DUP2(w2, wb.y); FMA2(acc[5][0], xd.x, w2, acc[5][0]); FMA2(acc[5][1], xd.y, w2, acc[5][1]);
            DUP2(w2, wb.z); FMA2(acc[6][0], xd.x, w2, acc[6][0]); FMA2(acc[6][1], xd.y, w2, acc[6][1]);
            DUP2(w2, wb.w); FMA2(acc[7][0], xd.x, w2, acc[7][0]); FMA2(acc[7][1], xd.y, w2, acc[7][1]);

            xd = xn; wa = wan; wb = wbn;
        }
    }

    // per-head 1/denom, applied once (packed multiply)
    const float4* dn4 = (const float4*)(g_denom + n * KK);
    float4 d0 = dn4[0], d1 = dn4[1];
    float inv[8];
    inv[0] = (deg > 0) ? __frcp_rn(d0.x) : 0.f;
    inv[1] = (deg > 0) ? __frcp_rn(d0.y) : 0.f;
    inv[2] = (deg > 0) ? __frcp_rn(d0.z) : 0.f;
    inv[3] = (deg > 0) ? __frcp_rn(d0.w) : 0.f;
    inv[4] = (deg > 0) ? __frcp_rn(d1.x) : 0.f;
    inv[5] = (deg > 0) ? __frcp_rn(d1.y) : 0.f;
    inv[6] = (deg > 0) ? __frcp_rn(d1.z) : 0.f;
    inv[7] = (deg > 0) ? __frcp_rn(d1.w) : 0.f;

    ulonglong2* gy2 = (ulonglong2*)g_y;
    #pragma unroll
    for (int k = 0; k < 8; k++) {
        ull iv;
        DUP2(iv, inv[k]);
        ulonglong2 o;
        MUL2(o.x, acc[k][0], iv);
        MUL2(o.y, acc[k][1], iv);
        gy2[(size_t)n * 256 + k * 32 + lane] = o;
    }

    __syncwarp();   // all lanes finished reading g_cnt/g_denom
    if (lane == 0) g_cnt[n] = 0;
    if (lane < KK) g_denom[n * KK + lane] = 0.f;
}

// ---------------- block-diagonal GEMM with packed f32x2 FMA ----------------
// out[n,k,:] = y[n,k,:] @ W_k.  Tile 128(n) x 64(h), BK=32, thread 8x4.
__global__ __launch_bounds__(256) void out_kernel(const float* __restrict__ W_enc,
                                                  float* __restrict__ out) {
    __shared__ float As[32][130];   // [d][row], 130 pad: 8B-aligned rows
    __shared__ float Ws[32][65];
    int k = blockIdx.y;
    int n0 = blockIdx.x * 128;
    int tid = threadIdx.x;
    int tx = tid & 15, ty = tid >> 4;
    int ty8 = ty * 8, tx4 = tx * 4;

    ull c[4][4];                    // [row-pair][cc], each holds rows (2j, 2j+1)
    #pragma unroll
    for (int j = 0; j < 4; j++)
        #pragma unroll
        for (int cc = 0; cc < 4; cc++) c[j][cc] = 0ull;

    for (int kk = 0; kk < DD; kk += 32) {
        #pragma unroll
        for (int p = 0; p < 16; p++) {
            int q = tid + 256 * p;
            int row = q >> 5, d = q & 31;
            int n = n0 + row;
            As[d][row] = (n < NN) ? g_y[(size_t)n * (KK * DD) + k * DD + kk + d] : 0.f;
        }
        #pragma unroll
        for (int p = 0; p < 8; p++) {
            int q = tid + 256 * p;
            int d = q >> 6, h = q & 63;
            Ws[d][h] = W_enc[(size_t)(kk + d) * KHD + k * HH + h];
        }
        __syncthreads();
        #pragma unroll
        for (int d = 0; d < 32; d++) {
            ull a[4];
            a[0] = *(const ull*)&As[d][ty8];
            a[1] = *(const ull*)&As[d][ty8 + 2];
            a[2] = *(const ull*)&As[d][ty8 + 4];
            a[3] = *(const ull*)&As[d][ty8 + 6];
            #pragma unroll
            for (int cc = 0; cc < 4; cc++) {
                ull bb;
                DUP2(bb, Ws[d][tx4 + cc]);
                FMA2(c[0][cc], a[0], bb, c[0][cc]);
                FMA2(c[1][cc], a[1], bb, c[1][cc]);
                FMA2(c[2][cc], a[2], bb, c[2][cc]);
                FMA2(c[3][cc], a[3], bb, c[3][cc]);
            }
        }
        __syncthreads();
    }
    #pragma unroll
    for (int j = 0; j < 4; j++) {
        int r0 = n0 + ty8 + 2 * j;
        #pragma unroll
        for (int cc = 0; cc < 4; cc++) {
            unsigned int lo, hi;
            asm("mov.b64 {%0, %1}, %2;" : "=r"(lo), "=r"(hi) : "l"(c[j][cc]));
            if (r0 < NN)
                out[(size_t)r0 * KHD + k * HH + tx4 + cc] = __uint_as_float(lo);
            if (r0 + 1 < NN)
                out[(size_t)(r0 + 1) * KHD + k * HH + tx4 + cc] = __uint_as_float(hi);
        }
    }
}

// ---------------- launch ----------------------------------------------------
// node_kernel now sits at my launch index 3 -> IT is the profiled kernel.
extern "C" void kernel_launch(void* const* d_in, const int* in_sizes, int n_in,
                              void* d_out, int out_size) {
    const float* node_feat = (const float*)d_in[0]; // (N,128)
    const float* edge_feat = (const float*)d_in[1]; // (E,3,128)
    const float* W_enc     = (const float*)d_in[2]; // (128,512)
    const float* attn_l    = (const float*)d_in[3]; // (1,8,64)
    const float* W_r       = (const float*)d_in[4]; // (8,128)
    const int*   dst       = (const int*)d_in[5];   // (E,)
    float* out = (float*)d_out;                     // (N,8,64)

    er_count_kernel<<<(NN + 7) / 8, 256>>>(node_feat, W_r, dst, W_enc, attn_l); // 0
    scan_kernel<<<1, 1024>>>();                                                 // 1
    edge_kernel<<<EDGE_GRID, 128>>>((const float4*)edge_feat, dst);             // 2
    node_kernel<<<(NN + 7) / 8, 256>>>();                                       // 3  <- profiled
    out_kernel<<<dim3((NN + 127) / 128, 8), 256>>>(W_enc, out);                 // 4
}